// round 12
// baseline (speedup 1.0000x reference)
#include <cuda_runtime.h>
#include <math.h>

#define NB 64
#define NANCH 6402
#define NANCHP 6416          // padded row (16B-aligned float4 rows); pad stays 0
#define NCLS 80
#define TOPK 200
#define MAXN 100
#define NCOEF 32

typedef unsigned long long ull;

// ---------------- scratch (__device__ globals: allocation-free rule) --------
__device__ __align__(16) float g_scoresT[(size_t)NB * NCLS * NANCHP]; // [b][c][anchP]
__device__ __align__(16) float g_bbox[(size_t)NB * NANCH * 4];        // decoded boxes
__device__ ull   g_mkey[(size_t)NB * NCLS * MAXN];   // per-class top-100 merge keys
__device__ int   g_anms[(size_t)NB * NCLS * TOPK];   // anchor id by rank k
__device__ __align__(16) float g_csel[(size_t)NB * MAXN * NCOEF];     // selected coeffs

struct AB { double v[5][3][4]; };   // host-computed anchor bases (numpy float64 path)

// order-preserving float<->uint (handles negatives for the -1.0 fillers)
__device__ __forceinline__ unsigned ford(float f) {
    unsigned u = __float_as_uint(f);
    return (u & 0x80000000u) ? ~u : (u | 0x80000000u);
}
__device__ __forceinline__ float iford(unsigned u) {
    return (u & 0x80000000u) ? __uint_as_float(u & 0x7FFFFFFFu) : __uint_as_float(~u);
}

__device__ __forceinline__ void fma2(ull& d, ull a, ull b) {
    asm("fma.rn.f32x2 %0, %1, %2, %0;" : "+l"(d) : "l"(a), "l"(b));
}

__device__ __forceinline__ void anch_decode(int anc, int& lvl, int& S, int& sp, int& a) {
    if (anc < 4800)      { lvl = 0; S = 1600; anc -= 0; }
    else if (anc < 6000) { lvl = 1; S = 400;  anc -= 4800; }
    else if (anc < 6300) { lvl = 2; S = 100;  anc -= 6000; }
    else if (anc < 6375) { lvl = 3; S = 25;   anc -= 6300; }
    else                 { lvl = 4; S = 9;    anc -= 6375; }
    sp = anc / 3;
    a  = anc - sp * 3;
}

// block-wide exclusive-scan of x; returns this thread's exclusive offset,
// sets total. Uses wsum[NW]; 2 internal barriers.
template <int NW>
__device__ __forceinline__ int block_scan(int x, int lane, int wid,
                                          volatile int* wsum, int& total) {
    int inc = x;
#pragma unroll
    for (int off = 1; off < 32; off <<= 1) {
        int y = __shfl_up_sync(0xffffffffu, inc, off);
        if (lane >= off) inc += y;
    }
    if (lane == 31) wsum[wid] = inc;
    __syncthreads();
    int woff = 0, tot = 0;
#pragma unroll
    for (int w = 0; w < NW; w++) { int s = wsum[w]; if (w < wid) woff += s; tot += s; }
    total = tot;
    __syncthreads();
    return woff + (inc - x);
}

// ============================================================================
// Kernel A (fused pre): bx<69 -> softmax role (threads 0..95 active),
// bx>=69 -> delta2bbox role. One launch, mask becomes the 4th (captured) one.
// ============================================================================
__global__ __launch_bounds__(256) void pre_kernel(const float* __restrict__ c0,
                                                  const float* __restrict__ c1,
                                                  const float* __restrict__ c2,
                                                  const float* __restrict__ c3,
                                                  const float* __restrict__ c4,
                                                  const float* __restrict__ bb0,
                                                  const float* __restrict__ bb1,
                                                  const float* __restrict__ bb2,
                                                  const float* __restrict__ bb3,
                                                  const float* __restrict__ bb4,
                                                  AB ab) {
    int bx = blockIdx.x;
    int b = blockIdx.y;
    __shared__ float sbuf[NCLS * 96];

    if (bx < 69) {
        // ---------------- softmax role ----------------
        const float* cls; int S, aoff, x0;
        if (bx < 50)      { cls = c0; S = 1600; aoff = 0;    x0 = bx; }
        else if (bx < 63) { cls = c1; S = 400;  aoff = 4800; x0 = bx - 50; }
        else if (bx < 67) { cls = c2; S = 100;  aoff = 6000; x0 = bx - 63; }
        else if (bx < 68) { cls = c3; S = 25;   aoff = 6300; x0 = 0; }
        else              { cls = c4; S = 9;    aoff = 6375; x0 = 0; }

        int t = threadIdx.x;
        if (t < 96) {
            int lane = t & 31;
            int a = t >> 5;
            int sp = x0 * 32 + lane;
            if (sp < S) {
                const float* base = cls + ((size_t)b * 243 + (size_t)a * 81) * S + sp;
                float v[81];
#pragma unroll
                for (int c = 0; c < 81; c++) v[c] = base[(size_t)c * S];
                float m = v[0];
#pragma unroll
                for (int c = 1; c < 81; c++) m = fmaxf(m, v[c]);
                float s = 0.f;
#pragma unroll
                for (int c = 0; c < 81; c++) { v[c] = expf(v[c] - m); s += v[c]; }
                float inv = 1.0f / s;
#pragma unroll
                for (int c = 0; c < 80; c++) sbuf[c * 96 + lane * 3 + a] = v[c] * inv;
            } else {
#pragma unroll
                for (int c = 0; c < 80; c++) sbuf[c * 96 + lane * 3 + a] = 0.f;
            }
        }
        __syncthreads();

        int remain = (S - x0 * 32) * 3;
        int cnt = remain < 96 ? remain : 96;
        size_t obase = (size_t)b * NCLS * NANCHP + aoff + (size_t)x0 * 96;
        if (t < cnt) {
            for (int c = 0; c < NCLS; c++)
                g_scoresT[obase + (size_t)c * NANCHP + t] = sbuf[c * 96 + t];
        }
    } else {
        // ---------------- bbox role ----------------
        int anc = (bx - 69) * 256 + threadIdx.x;
        if (anc >= NANCH) return;

        int lvl, S, sp, a;
        anch_decode(anc, lvl, S, sp, a);
        int f, bs;
        const float* bp;
        switch (lvl) {
            case 0: f = 40; bs = 8;   bp = bb0; break;
            case 1: f = 20; bs = 16;  bp = bb1; break;
            case 2: f = 10; bs = 32;  bp = bb2; break;
            case 3: f = 5;  bs = 64;  bp = bb3; break;
            default: f = 3; bs = 128; bp = bb4; break;
        }
        int x = sp % f, y = sp / f;
        double shx = (double)(x * bs), shy = (double)(y * bs);
        float ax1 = (float)(ab.v[lvl][a][0] + shx);
        float ay1 = (float)(ab.v[lvl][a][1] + shy);
        float ax2 = (float)(ab.v[lvl][a][2] + shx);
        float ay2 = (float)(ab.v[lvl][a][3] + shy);

        size_t di = ((size_t)b * 12 + (size_t)a * 4) * S + sp;
        float dx = bp[di] * 0.1f;
        float dy = bp[di + (size_t)S] * 0.1f;
        float dw = bp[di + 2 * (size_t)S] * 0.2f;
        float dh = bp[di + 3 * (size_t)S] * 0.2f;
        const float R = 4.135166556742356f;
        dw = fminf(fmaxf(dw, -R), R);
        dh = fminf(fmaxf(dh, -R), R);

        float px = (ax1 + ax2) * 0.5f, py = (ay1 + ay2) * 0.5f;
        float pw = ax2 - ax1, ph = ay2 - ay1;
        float gx = px + pw * dx, gy = py + ph * dy;
        float gw = pw * expf(dw), gh = ph * expf(dh);
        float4 o;
        o.x = fminf(fmaxf(gx - 0.5f * gw, 0.f), 320.f);
        o.y = fminf(fmaxf(gy - 0.5f * gh, 0.f), 320.f);
        o.z = fminf(fmaxf(gx + 0.5f * gw, 0.f), 320.f);
        o.w = fminf(fmaxf(gy + 0.5f * gh, 0.f), 320.f);
        *(float4*)&g_bbox[((size_t)b * NANCH + anc) * 4] = o;
    }
}

// ============================================================================
// Kernel C (fused): per-(batch,class): exact stable top-200 (early-exit
// bit-search + scan-compaction), bitonic sort, fast-NMS (score-gated,
// single-predicate hot path, exact rare path), stable partition.
// ============================================================================
__global__ __launch_bounds__(256, 6) void nms_kernel() {
    int c = blockIdx.x, b = blockIdx.y;
    int tid = threadIdx.x;
    int lane = tid & 31, wid = tid >> 5;
    __shared__ int s_hist[2][8];
    __shared__ int s_wsum[8];
    __shared__ int s_wsum2[8];
    __shared__ int s_taken;
    __shared__ ull skey[256];
    __shared__ float4 sbx[TOPK];
    __shared__ float sar[TOPK];      // raw areas (exact path)
    __shared__ float sar3[TOPK];     // C3-prescaled areas (hot path)

    const float* srow = g_scoresT + ((size_t)b * NCLS + c) * NANCHP;
    unsigned v[28];
#pragma unroll
    for (int r = 0; r < 7; r++) {
        int f4 = r * 256 + tid;
        if (f4 < NANCHP / 4) {
            float4 t = *(const float4*)(srow + f4 * 4);
            v[r * 4 + 0] = __float_as_uint(t.x);
            v[r * 4 + 1] = __float_as_uint(t.y);
            v[r * 4 + 2] = __float_as_uint(t.z);
            v[r * 4 + 3] = __float_as_uint(t.w);
        } else {
            v[r * 4 + 0] = v[r * 4 + 1] = v[r * 4 + 2] = v[r * 4 + 3] = 0u;
        }
    }

    // ---- early-exit bit-search: 200 <= count(v >= T) <= 256, 1 barrier/round --
    unsigned T = 0;
    int cur = 1 << 30, pp = 0;
    for (int bit = 29; bit >= 0; bit--) {
        if (cur <= 256) break;
        unsigned cand = T | (1u << bit);
        int cnt = 0;
#pragma unroll
        for (int e = 0; e < 28; e++) cnt += (v[e] >= cand);
        cnt = (int)__reduce_add_sync(0xffffffffu, (unsigned)cnt);
        if (lane == 0) s_hist[pp][wid] = cnt;
        __syncthreads();
        int tot = 0;
#pragma unroll
        for (int w = 0; w < 8; w++) tot += s_hist[pp][w];
        if (tot >= TOPK) { T = cand; cur = tot; }
        pp ^= 1;
    }

    skey[tid] = ~0ULL;
    __syncthreads();

    if (cur <= 256) {
        // collect all v >= T via scan (no atomics); sort restores exact order
        int ct = 0;
#pragma unroll
        for (int e = 0; e < 28; e++) ct += (v[e] >= T);
        int tot;
        int pos = block_scan<8>(ct, lane, wid, s_wsum, tot);
#pragma unroll
        for (int r = 0; r < 7; r++)
#pragma unroll
            for (int q = 0; q < 4; q++) {
                int e = r * 4 + q;
                if (v[e] >= T) {
                    int i = (r * 256 + tid) * 4 + q;
                    ull key = ((ull)v[e] << 32) | (unsigned)(~(unsigned)i);
                    skey[pos++] = ~key;
                }
            }
        __syncthreads();
    } else {
        // pathological mass-tie fallback: v > T, then equal-T smallest indices
        int cg = 0;
#pragma unroll
        for (int e = 0; e < 28; e++) cg += (v[e] > T);
        int cnt_gt;
        int pos = block_scan<8>(cg, lane, wid, s_wsum, cnt_gt);
        int need_eq = TOPK - cnt_gt;
#pragma unroll
        for (int r = 0; r < 7; r++)
#pragma unroll
            for (int q = 0; q < 4; q++) {
                int e = r * 4 + q;
                if (v[e] > T) {
                    int i = (r * 256 + tid) * 4 + q;
                    ull key = ((ull)v[e] << 32) | (unsigned)(~(unsigned)i);
                    skey[pos++] = ~key;
                }
            }
        if (tid == 0) s_taken = 0;
        __syncthreads();
        // i-order = (r, tid, q) lexicographic == ascending anchor index
        for (int r = 0; r < 7; r++) {
            __syncthreads();
            int taken = s_taken;
            if (taken >= need_eq) continue;
            int ec = 0;
            bool mq[4];
#pragma unroll
            for (int q = 0; q < 4; q++) {
                mq[q] = (v[r * 4 + q] == T);
                ec += mq[q];
            }
            int tot2;
            int base = block_scan<8>(ec, lane, wid, s_wsum, tot2);
            int o = taken + base;
#pragma unroll
            for (int q = 0; q < 4; q++)
                if (mq[q]) {
                    if (o < need_eq) {
                        int i = (r * 256 + tid) * 4 + q;
                        ull key = ((ull)T << 32) | (unsigned)(~(unsigned)i);
                        skey[cnt_gt + o] = ~key;
                    }
                    o++;
                }
            if (tid == 0) s_taken = taken + tot2;
        }
        __syncthreads();
    }

    // ---- bitonic sort 256 (ascending ~key == desc score, asc anchor) ----
    for (int k2 = 2; k2 <= 256; k2 <<= 1)
        for (int j = k2 >> 1; j > 0; j >>= 1) {
            __syncthreads();
            int ixj = tid ^ j;
            if (ixj > tid) {
                ull A = skey[tid], B = skey[ixj];
                bool up = ((tid & k2) == 0);
                if ((A > B) == up) { skey[tid] = B; skey[ixj] = A; }
            }
        }
    __syncthreads();

    // ---- gather boxes for fast-NMS ----
    const float C3 = 0.3333290f;
    float score = -2.f;
    if (tid < TOPK) {
        ull key = ~skey[tid];
        int anc = (int)(~(unsigned)(key & 0xFFFFFFFFu));
        score = __uint_as_float((unsigned)(key >> 32));
        float4 bx = *(const float4*)&g_bbox[((size_t)b * NANCH + anc) * 4];
        sbx[tid] = bx;
        float ar = (bx.z - bx.x) * (bx.w - bx.y);
        sar[tid] = ar;
        sar3[tid] = C3 * ar;
        g_anms[((size_t)b * NCLS + c) * TOPK + tid] = anc;
    }
    __syncthreads();

    // ---- fast-NMS. Threads with score <= SCORE_THR can never be kept
    // (kp needs score > 0.05 and viol is used nowhere else), so they skip
    // their IoU loop entirely; they still act as suppressors via sbx/sar3.
    // Hot path: ovp > sar3[i2]+aj3 (superset gate, margin-proven incl.
    // split rounding + 1e-6-clamp corner). Rare path replays the exact
    // original lo/hi/double decision. ----
    bool viol = false;
    if (tid > 0 && tid < TOPK && score > 0.05f) {
        float4 B = sbx[tid];
        float aj3 = sar3[tid];
#pragma unroll 4
        for (int i2 = 0; i2 < tid; i2++) {
            float4 A = sbx[i2];
            float w = fminf(A.z, B.z) - fmaxf(A.x, B.x);
            float h = fminf(A.w, B.w) - fmaxf(A.y, B.y);
            float ovp = fmaxf(w, 0.f) * h;          // == ov when w,h > 0
            if (ovp > sar3[i2] + aj3) {             // rare candidate
                float ov = fmaxf(w, 0.f) * fmaxf(h, 0.f);
                float un = fmaxf(sar[i2] + sar[tid] - ov, 1e-6f);
                if (ov > 0.49999952f * un) {
                    if (ov > 0.50000048f * un ||
                        (double)ov > 0.5000000298023223876953125 * (double)un) {
                        viol = true; break;
                    }
                }
            }
        }
    }
    bool kp = (tid < TOPK) && !viol && (score > 0.05f);

    // ---- stable partition == sort by (masked desc, flat asc) ----
    bool isk = (tid < TOPK) && kp;
    bool isn = (tid < TOPK) && !kp;
    unsigned mK = __ballot_sync(0xffffffffu, isk);
    unsigned mN = __ballot_sync(0xffffffffu, isn);
    if (lane == 0) { s_wsum[wid] = __popc(mK); s_wsum2[wid] = __popc(mN); }
    __syncthreads();
    int cntK = 0, preK = 0, preN = 0;
#pragma unroll
    for (int w = 0; w < 8; w++) {
        cntK += s_wsum[w];
        if (w < wid) { preK += s_wsum[w]; preN += s_wsum2[w]; }
    }
    preK += __popc(mK & ((1u << lane) - 1u));
    preN += __popc(mN & ((1u << lane) - 1u));
    __syncthreads();                    // skey reads done; reuse as smk
    if (tid < TOPK) {
        float masked = kp ? score : -1.0f;
        int flat = c * TOPK + tid;
        ull key2 = ((ull)ford(masked) << 14) | (unsigned)(16383 - flat);
        int pos = kp ? preK : (cntK + preN);
        skey[pos] = key2;
    }
    __syncthreads();
    if (tid < MAXN)
        g_mkey[((size_t)b * NCLS + c) * MAXN + tid] = skey[tid];
}

// ============================================================================
// Kernel D: per-batch global top-100 over 80x100 keys (exact lax.top_k).
// 1024 threads x 8 keys; 2-bit-per-round search with 3 candidates and
// warp-level cross-reduction.
// ============================================================================
__global__ __launch_bounds__(1024) void merge_kernel(const float* __restrict__ f0,
                                                     const float* __restrict__ f1,
                                                     const float* __restrict__ f2,
                                                     const float* __restrict__ f3,
                                                     const float* __restrict__ f4,
                                                     float* __restrict__ out) {
    int b = blockIdx.x, tid = threadIdx.x;
    int lane = tid & 31, wid = tid >> 5;
    __shared__ int s_w3[32 * 3];
    __shared__ int s_tot[3];
    __shared__ int s_cnt;
    __shared__ ull skey[128];
    __shared__ int s_anchor[MAXN];

    const ull* mk = g_mkey + (size_t)b * NCLS * MAXN;
    ull w[8];
#pragma unroll
    for (int r = 0; r < 8; r++) {
        int i = r * 1024 + tid;
        w[r] = (i < NCLS * MAXN) ? mk[i] : 0ULL;
    }

    // 2-bit-per-round bit-search (keys unique -> terminates with count<=128)
    ull T = 0;
    int cur = 1 << 30;
    for (int bit = 45; bit >= 1; bit -= 2) {
        if (cur <= 128) break;
        ull cA = T | (1ULL << bit);
        ull cB = cA | (1ULL << (bit - 1));
        ull cC = T | (1ULL << (bit - 1));
        int nA = 0, nB = 0, nC = 0;
#pragma unroll
        for (int r = 0; r < 8; r++) {
            nA += (w[r] >= cA);
            nB += (w[r] >= cB);
            nC += (w[r] >= cC);
        }
        nA = (int)__reduce_add_sync(0xffffffffu, (unsigned)nA);
        nB = (int)__reduce_add_sync(0xffffffffu, (unsigned)nB);
        nC = (int)__reduce_add_sync(0xffffffffu, (unsigned)nC);
        if (lane == 0) {
            s_w3[wid * 3 + 0] = nA;
            s_w3[wid * 3 + 1] = nB;
            s_w3[wid * 3 + 2] = nC;
        }
        __syncthreads();
        if (wid < 3) {
            int x = s_w3[lane * 3 + wid];
#pragma unroll
            for (int off = 16; off; off >>= 1) x += __shfl_xor_sync(0xffffffffu, x, off);
            if (lane == 0) s_tot[wid] = x;
        }
        __syncthreads();
        int tA = s_tot[0], tB = s_tot[1], tC = s_tot[2];
        if (tA >= MAXN) {
            if (tB >= MAXN) { T = cB; cur = tB; }
            else            { T = cA; cur = tA; }
        } else {
            if (tC >= MAXN) { T = cC; cur = tC; }
        }
        __syncthreads();
    }

    if (tid == 0) s_cnt = 0;
    if (tid < 128) skey[tid] = ~0ULL;
    __syncthreads();
#pragma unroll
    for (int r = 0; r < 8; r++)
        if (w[r] >= T) { int p = atomicAdd(&s_cnt, 1); skey[p] = ~w[r]; }
    __syncthreads();

    for (int k2 = 2; k2 <= 128; k2 <<= 1)
        for (int j = k2 >> 1; j > 0; j >>= 1) {
            __syncthreads();
            if (tid < 128) {
                int ixj = tid ^ j;
                if (ixj > tid) {
                    ull A = skey[tid], B = skey[ixj];
                    bool up = ((tid & k2) == 0);
                    if ((A > B) == up) { skey[tid] = B; skey[ixj] = A; }
                }
            }
        }
    __syncthreads();

    if (tid < MAXN) {
        ull key = ~skey[tid];
        int flat = 16383 - (int)(key & 0x3FFFULL);
        int c = flat / TOPK, k = flat - c * TOPK;
        float val = iford((unsigned)(key >> 14));
        int anc = g_anms[((size_t)b * NCLS + c) * TOPK + k];
        float4 bx = *(const float4*)&g_bbox[((size_t)b * NANCH + anc) * 4];
        float* dr = out + ((size_t)b * MAXN + tid) * 5;
        dr[0] = bx.x; dr[1] = bx.y; dr[2] = bx.z; dr[3] = bx.w; dr[4] = val;
        out[(size_t)NB * MAXN * 5 + (size_t)b * MAXN + tid] = (float)c;
        s_anchor[tid] = anc;
    }
    __syncthreads();

    const float* cf[5] = { f0, f1, f2, f3, f4 };
    for (int idx = tid; idx < MAXN * NCOEF; idx += 1024) {
        int n = idx / NCOEF, j = idx - n * NCOEF;
        int anc = s_anchor[n];
        int lvl, S, sp, a;
        anch_decode(anc, lvl, S, sp, a);
        const float* cp = cf[lvl];
        g_csel[((size_t)b * MAXN + n) * NCOEF + j] =
            cp[((size_t)b * 96 + (size_t)(a * NCOEF + j)) * S + sp];
    }
}

// ============================================================================
// Kernel E: masks = sigmoid(proto @ csel^T). Pair-interleaved mapping
// {pg, pg+16, pg+32, pg+48} so BOTH epilogue phases use all 256 threads.
// Packed f32x2 FMA, staged coalesced stores. 128 pixels/block.
// ============================================================================
__global__ __launch_bounds__(256) void mask_kernel(const float* __restrict__ proto,
                                                   float* __restrict__ out) {
    int b = blockIdx.y;
    int pix0 = blockIdx.x * 128;
    int tid = threadIdx.x;
    int pg = tid >> 4;       // 0..15 -> pairs pg, pg+16, pg+32, pg+48
    int ng = tid & 15;       // 0..15 -> n = ng*7 .. ng*7+6
    __shared__ ull scs2[112 * 35];     // [n][k] coeff dup both halves
    __shared__ ull sproto2[64 * 34];   // [pair][k] = (proto[2p], proto[2p+1])

    for (int idx = tid; idx < 112 * 8; idx += 256) {
        int n = idx >> 3, k4 = idx & 7;
        float4 cv = (n < MAXN)
            ? *(const float4*)(g_csel + ((size_t)b * MAXN + n) * NCOEF + k4 * 4)
            : make_float4(0.f, 0.f, 0.f, 0.f);
        ull p;
        asm("mov.b64 %0, {%1, %1};" : "=l"(p) : "f"(cv.x)); scs2[n * 35 + k4 * 4 + 0] = p;
        asm("mov.b64 %0, {%1, %1};" : "=l"(p) : "f"(cv.y)); scs2[n * 35 + k4 * 4 + 1] = p;
        asm("mov.b64 %0, {%1, %1};" : "=l"(p) : "f"(cv.z)); scs2[n * 35 + k4 * 4 + 2] = p;
        asm("mov.b64 %0, {%1, %1};" : "=l"(p) : "f"(cv.w)); scs2[n * 35 + k4 * 4 + 3] = p;
    }
    for (int idx = tid; idx < 128 * 8; idx += 256) {
        int px = idx >> 3, k4 = idx & 7;
        float4 pv = *(const float4*)(proto + ((size_t)b * 6400 + pix0 + px) * NCOEF + k4 * 4);
        float* dst = (float*)&sproto2[(px >> 1) * 34 + k4 * 4];
        int h = px & 1;
        dst[0 + h] = pv.x; dst[2 + h] = pv.y; dst[4 + h] = pv.z; dst[6 + h] = pv.w;
    }
    __syncthreads();

    ull acc[4][7];
#pragma unroll
    for (int i = 0; i < 4; i++)
#pragma unroll
        for (int j = 0; j < 7; j++) acc[i][j] = 0ULL;

#pragma unroll
    for (int k = 0; k < NCOEF; k++) {
        ull pv[4];
#pragma unroll
        for (int i = 0; i < 4; i++) pv[i] = sproto2[(pg + 16 * i) * 34 + k];
#pragma unroll
        for (int j = 0; j < 7; j++) {
            ull cv = scs2[(ng * 7 + j) * 35 + k];
#pragma unroll
            for (int i = 0; i < 4; i++) fma2(acc[i][j], pv[i], cv);
        }
    }

    size_t mbase = (size_t)NB * MAXN * 5 + (size_t)NB * MAXN;
    float* stage = (float*)scs2;        // 31.4KB >= 64*100*4
#pragma unroll
    for (int ch = 0; ch < 2; ch++) {
        __syncthreads();
#pragma unroll
        for (int ii = 0; ii < 2; ii++) {
            int i = 2 * ch + ii;                    // pair index slot
            int pl = (pg + 16 * ii) * 2;            // local px (even) in phase
#pragma unroll
            for (int j = 0; j < 7; j++) {
                int n = ng * 7 + j;
                if (n < MAXN) {
                    float lo, hi;
                    asm("mov.b64 {%0, %1}, %2;" : "=f"(lo), "=f"(hi) : "l"(acc[i][j]));
                    stage[pl * 100 + n]       = __fdividef(1.0f, 1.0f + __expf(-lo));
                    stage[(pl + 1) * 100 + n] = __fdividef(1.0f, 1.0f + __expf(-hi));
                }
            }
        }
        __syncthreads();
        float4* o4 = (float4*)(out + mbase + ((size_t)b * 6400 + pix0 + ch * 64) * MAXN);
        const float4* s4 = (const float4*)stage;
        for (int idx = tid; idx < 64 * MAXN / 4; idx += 256) o4[idx] = s4[idx];
    }
}

// ============================================================================
extern "C" void kernel_launch(void* const* d_in, const int* in_sizes, int n_in,
                              void* d_out, int out_size) {
    const float* cls[5]; const float* box[5]; const float* cf[5];
    for (int i = 0; i < 5; i++) {
        cls[i] = (const float*)d_in[i];
        box[i] = (const float*)d_in[5 + i];
        cf[i]  = (const float*)d_in[10 + i];
    }
    const float* proto = (const float*)d_in[15];
    float* out = (float*)d_out;

    // host-side anchor bases (exact numpy float64 computation order)
    AB ab;
    const int BS[5] = {8, 16, 32, 64, 128};
    const double RT[3] = {0.5, 1.0, 2.0};
    for (int l = 0; l < 5; l++)
        for (int a = 0; a < 3; a++) {
            double hr = sqrt(RT[a]);
            double wr = 1.0 / hr;
            double ws = ((double)BS[l] * wr) * 3.0;
            double hs = ((double)BS[l] * hr) * 3.0;
            double cc = (double)BS[l] / 2.0;
            ab.v[l][a][0] = cc - 0.5 * ws;
            ab.v[l][a][1] = cc - 0.5 * hs;
            ab.v[l][a][2] = cc + 0.5 * ws;
            ab.v[l][a][3] = cc + 0.5 * hs;
        }

    dim3 gp(95, NB);       // 69 softmax blocks + 26 bbox blocks per batch
    pre_kernel<<<gp, 256>>>(cls[0], cls[1], cls[2], cls[3], cls[4],
                            box[0], box[1], box[2], box[3], box[4], ab);
    dim3 gn(NCLS, NB);
    nms_kernel<<<gn, 256>>>();
    merge_kernel<<<NB, 1024>>>(cf[0], cf[1], cf[2], cf[3], cf[4], out);
    dim3 gm(50, NB);
    mask_kernel<<<gm, 256>>>(proto, out);
}

// round 13
// speedup vs baseline: 1.0126x; 1.0126x over previous
#include <cuda_runtime.h>
#include <math.h>

#define NB 64
#define NANCH 6402
#define NANCHP 6416          // padded row (16B-aligned float4 rows); pad stays 0
#define NCLS 80
#define TOPK 200
#define MAXN 100
#define NCOEF 32

typedef unsigned long long ull;

// ---------------- scratch (__device__ globals: allocation-free rule) --------
__device__ __align__(16) float g_scoresT[(size_t)NB * NCLS * NANCHP]; // [b][c][anchP]
__device__ __align__(16) float g_bbox[(size_t)NB * NANCH * 4];        // decoded boxes
__device__ ull   g_mkey[(size_t)NB * NCLS * MAXN];   // per-class top-100 merge keys
__device__ int   g_anms[(size_t)NB * NCLS * TOPK];   // anchor id by rank k
__device__ __align__(16) float g_csel[(size_t)NB * MAXN * NCOEF];     // selected coeffs

struct AB { double v[5][3][4]; };   // host-computed anchor bases (numpy float64 path)

// order-preserving float<->uint (handles negatives for the -1.0 fillers)
__device__ __forceinline__ unsigned ford(float f) {
    unsigned u = __float_as_uint(f);
    return (u & 0x80000000u) ? ~u : (u | 0x80000000u);
}
__device__ __forceinline__ float iford(unsigned u) {
    return (u & 0x80000000u) ? __uint_as_float(u & 0x7FFFFFFFu) : __uint_as_float(~u);
}

__device__ __forceinline__ void fma2(ull& d, ull a, ull b) {
    asm("fma.rn.f32x2 %0, %1, %2, %0;" : "+l"(d) : "l"(a), "l"(b));
}

__device__ __forceinline__ void anch_decode(int anc, int& lvl, int& S, int& sp, int& a) {
    if (anc < 4800)      { lvl = 0; S = 1600; anc -= 0; }
    else if (anc < 6000) { lvl = 1; S = 400;  anc -= 4800; }
    else if (anc < 6300) { lvl = 2; S = 100;  anc -= 6000; }
    else if (anc < 6375) { lvl = 3; S = 25;   anc -= 6300; }
    else                 { lvl = 4; S = 9;    anc -= 6375; }
    sp = anc / 3;
    a  = anc - sp * 3;
}

// block-wide exclusive-scan of x; returns this thread's exclusive offset,
// sets total. Uses wsum[NW]; 2 internal barriers.
template <int NW>
__device__ __forceinline__ int block_scan(int x, int lane, int wid,
                                          volatile int* wsum, int& total) {
    int inc = x;
#pragma unroll
    for (int off = 1; off < 32; off <<= 1) {
        int y = __shfl_up_sync(0xffffffffu, inc, off);
        if (lane >= off) inc += y;
    }
    if (lane == 31) wsum[wid] = inc;
    __syncthreads();
    int woff = 0, tot = 0;
#pragma unroll
    for (int w = 0; w < NW; w++) { int s = wsum[w]; if (w < wid) woff += s; tot += s; }
    total = tot;
    __syncthreads();
    return woff + (inc - x);
}

// ============================================================================
// Kernel A (fused pre): bx<69 -> softmax role, bx>=69 -> delta2bbox role.
// ============================================================================
__global__ __launch_bounds__(256) void pre_kernel(const float* __restrict__ c0,
                                                  const float* __restrict__ c1,
                                                  const float* __restrict__ c2,
                                                  const float* __restrict__ c3,
                                                  const float* __restrict__ c4,
                                                  const float* __restrict__ bb0,
                                                  const float* __restrict__ bb1,
                                                  const float* __restrict__ bb2,
                                                  const float* __restrict__ bb3,
                                                  const float* __restrict__ bb4,
                                                  AB ab) {
    int bx = blockIdx.x;
    int b = blockIdx.y;
    __shared__ float sbuf[NCLS * 96];

    if (bx < 69) {
        const float* cls; int S, aoff, x0;
        if (bx < 50)      { cls = c0; S = 1600; aoff = 0;    x0 = bx; }
        else if (bx < 63) { cls = c1; S = 400;  aoff = 4800; x0 = bx - 50; }
        else if (bx < 67) { cls = c2; S = 100;  aoff = 6000; x0 = bx - 63; }
        else if (bx < 68) { cls = c3; S = 25;   aoff = 6300; x0 = 0; }
        else              { cls = c4; S = 9;    aoff = 6375; x0 = 0; }

        int t = threadIdx.x;
        if (t < 96) {
            int lane = t & 31;
            int a = t >> 5;
            int sp = x0 * 32 + lane;
            if (sp < S) {
                const float* base = cls + ((size_t)b * 243 + (size_t)a * 81) * S + sp;
                float v[81];
#pragma unroll
                for (int c = 0; c < 81; c++) v[c] = base[(size_t)c * S];
                float m = v[0];
#pragma unroll
                for (int c = 1; c < 81; c++) m = fmaxf(m, v[c]);
                float s = 0.f;
#pragma unroll
                for (int c = 0; c < 81; c++) { v[c] = expf(v[c] - m); s += v[c]; }
                float inv = 1.0f / s;
#pragma unroll
                for (int c = 0; c < 80; c++) sbuf[c * 96 + lane * 3 + a] = v[c] * inv;
            } else {
#pragma unroll
                for (int c = 0; c < 80; c++) sbuf[c * 96 + lane * 3 + a] = 0.f;
            }
        }
        __syncthreads();

        int remain = (S - x0 * 32) * 3;
        int cnt = remain < 96 ? remain : 96;
        size_t obase = (size_t)b * NCLS * NANCHP + aoff + (size_t)x0 * 96;
        if (t < cnt) {
            for (int c = 0; c < NCLS; c++)
                g_scoresT[obase + (size_t)c * NANCHP + t] = sbuf[c * 96 + t];
        }
    } else {
        int anc = (bx - 69) * 256 + threadIdx.x;
        if (anc >= NANCH) return;

        int lvl, S, sp, a;
        anch_decode(anc, lvl, S, sp, a);
        int f, bs;
        const float* bp;
        switch (lvl) {
            case 0: f = 40; bs = 8;   bp = bb0; break;
            case 1: f = 20; bs = 16;  bp = bb1; break;
            case 2: f = 10; bs = 32;  bp = bb2; break;
            case 3: f = 5;  bs = 64;  bp = bb3; break;
            default: f = 3; bs = 128; bp = bb4; break;
        }
        int x = sp % f, y = sp / f;
        double shx = (double)(x * bs), shy = (double)(y * bs);
        float ax1 = (float)(ab.v[lvl][a][0] + shx);
        float ay1 = (float)(ab.v[lvl][a][1] + shy);
        float ax2 = (float)(ab.v[lvl][a][2] + shx);
        float ay2 = (float)(ab.v[lvl][a][3] + shy);

        size_t di = ((size_t)b * 12 + (size_t)a * 4) * S + sp;
        float dx = bp[di] * 0.1f;
        float dy = bp[di + (size_t)S] * 0.1f;
        float dw = bp[di + 2 * (size_t)S] * 0.2f;
        float dh = bp[di + 3 * (size_t)S] * 0.2f;
        const float R = 4.135166556742356f;
        dw = fminf(fmaxf(dw, -R), R);
        dh = fminf(fmaxf(dh, -R), R);

        float px = (ax1 + ax2) * 0.5f, py = (ay1 + ay2) * 0.5f;
        float pw = ax2 - ax1, ph = ay2 - ay1;
        float gx = px + pw * dx, gy = py + ph * dy;
        float gw = pw * expf(dw), gh = ph * expf(dh);
        float4 o;
        o.x = fminf(fmaxf(gx - 0.5f * gw, 0.f), 320.f);
        o.y = fminf(fmaxf(gy - 0.5f * gh, 0.f), 320.f);
        o.z = fminf(fmaxf(gx + 0.5f * gw, 0.f), 320.f);
        o.w = fminf(fmaxf(gy + 0.5f * gh, 0.f), 320.f);
        *(float4*)&g_bbox[((size_t)b * NANCH + anc) * 4] = o;
    }
}

// ============================================================================
// Kernel C (fused): per-(batch,class): exact stable top-200 (early-exit
// bit-search + scan-compaction), bitonic sort, fast-NMS (score-gated,
// single-predicate hot path, exact rare path), stable partition.
// ============================================================================
__global__ __launch_bounds__(256, 6) void nms_kernel() {
    int c = blockIdx.x, b = blockIdx.y;
    int tid = threadIdx.x;
    int lane = tid & 31, wid = tid >> 5;
    __shared__ int s_hist[2][8];
    __shared__ int s_wsum[8];
    __shared__ int s_wsum2[8];
    __shared__ int s_taken;
    __shared__ ull skey[256];
    __shared__ float4 sbx[TOPK];
    __shared__ float sar[TOPK];      // raw areas (exact path)
    __shared__ float sar3[TOPK];     // C3-prescaled areas (hot path)

    const float* srow = g_scoresT + ((size_t)b * NCLS + c) * NANCHP;
    unsigned v[28];
#pragma unroll
    for (int r = 0; r < 7; r++) {
        int f4 = r * 256 + tid;
        if (f4 < NANCHP / 4) {
            float4 t = *(const float4*)(srow + f4 * 4);
            v[r * 4 + 0] = __float_as_uint(t.x);
            v[r * 4 + 1] = __float_as_uint(t.y);
            v[r * 4 + 2] = __float_as_uint(t.z);
            v[r * 4 + 3] = __float_as_uint(t.w);
        } else {
            v[r * 4 + 0] = v[r * 4 + 1] = v[r * 4 + 2] = v[r * 4 + 3] = 0u;
        }
    }

    // ---- early-exit bit-search: 200 <= count(v >= T) <= 256, 1 barrier/round --
    unsigned T = 0;
    int cur = 1 << 30, pp = 0;
    for (int bit = 29; bit >= 0; bit--) {
        if (cur <= 256) break;
        unsigned cand = T | (1u << bit);
        int cnt = 0;
#pragma unroll
        for (int e = 0; e < 28; e++) cnt += (v[e] >= cand);
        cnt = (int)__reduce_add_sync(0xffffffffu, (unsigned)cnt);
        if (lane == 0) s_hist[pp][wid] = cnt;
        __syncthreads();
        int tot = 0;
#pragma unroll
        for (int w = 0; w < 8; w++) tot += s_hist[pp][w];
        if (tot >= TOPK) { T = cand; cur = tot; }
        pp ^= 1;
    }

    skey[tid] = ~0ULL;
    __syncthreads();

    if (cur <= 256) {
        // collect all v >= T via scan (no atomics); sort restores exact order
        int ct = 0;
#pragma unroll
        for (int e = 0; e < 28; e++) ct += (v[e] >= T);
        int tot;
        int pos = block_scan<8>(ct, lane, wid, s_wsum, tot);
#pragma unroll
        for (int r = 0; r < 7; r++)
#pragma unroll
            for (int q = 0; q < 4; q++) {
                int e = r * 4 + q;
                if (v[e] >= T) {
                    int i = (r * 256 + tid) * 4 + q;
                    ull key = ((ull)v[e] << 32) | (unsigned)(~(unsigned)i);
                    skey[pos++] = ~key;
                }
            }
        __syncthreads();
    } else {
        // pathological mass-tie fallback: v > T, then equal-T smallest indices
        int cg = 0;
#pragma unroll
        for (int e = 0; e < 28; e++) cg += (v[e] > T);
        int cnt_gt;
        int pos = block_scan<8>(cg, lane, wid, s_wsum, cnt_gt);
        int need_eq = TOPK - cnt_gt;
#pragma unroll
        for (int r = 0; r < 7; r++)
#pragma unroll
            for (int q = 0; q < 4; q++) {
                int e = r * 4 + q;
                if (v[e] > T) {
                    int i = (r * 256 + tid) * 4 + q;
                    ull key = ((ull)v[e] << 32) | (unsigned)(~(unsigned)i);
                    skey[pos++] = ~key;
                }
            }
        if (tid == 0) s_taken = 0;
        __syncthreads();
        // i-order = (r, tid, q) lexicographic == ascending anchor index
        for (int r = 0; r < 7; r++) {
            __syncthreads();
            int taken = s_taken;
            if (taken >= need_eq) continue;
            int ec = 0;
            bool mq[4];
#pragma unroll
            for (int q = 0; q < 4; q++) {
                mq[q] = (v[r * 4 + q] == T);
                ec += mq[q];
            }
            int tot2;
            int base = block_scan<8>(ec, lane, wid, s_wsum, tot2);
            int o = taken + base;
#pragma unroll
            for (int q = 0; q < 4; q++)
                if (mq[q]) {
                    if (o < need_eq) {
                        int i = (r * 256 + tid) * 4 + q;
                        ull key = ((ull)T << 32) | (unsigned)(~(unsigned)i);
                        skey[cnt_gt + o] = ~key;
                    }
                    o++;
                }
            if (tid == 0) s_taken = taken + tot2;
        }
        __syncthreads();
    }

    // ---- bitonic sort 256 (ascending ~key == desc score, asc anchor) ----
    for (int k2 = 2; k2 <= 256; k2 <<= 1)
        for (int j = k2 >> 1; j > 0; j >>= 1) {
            __syncthreads();
            int ixj = tid ^ j;
            if (ixj > tid) {
                ull A = skey[tid], B = skey[ixj];
                bool up = ((tid & k2) == 0);
                if ((A > B) == up) { skey[tid] = B; skey[ixj] = A; }
            }
        }
    __syncthreads();

    // ---- gather boxes for fast-NMS ----
    const float C3 = 0.3333290f;
    float score = -2.f;
    if (tid < TOPK) {
        ull key = ~skey[tid];
        int anc = (int)(~(unsigned)(key & 0xFFFFFFFFu));
        score = __uint_as_float((unsigned)(key >> 32));
        float4 bx = *(const float4*)&g_bbox[((size_t)b * NANCH + anc) * 4];
        sbx[tid] = bx;
        float ar = (bx.z - bx.x) * (bx.w - bx.y);
        sar[tid] = ar;
        sar3[tid] = C3 * ar;
        g_anms[((size_t)b * NCLS + c) * TOPK + tid] = anc;
    }
    __syncthreads();

    // ---- fast-NMS (score-gated; exact) ----
    bool viol = false;
    if (tid > 0 && tid < TOPK && score > 0.05f) {
        float4 B = sbx[tid];
        float aj3 = sar3[tid];
#pragma unroll 4
        for (int i2 = 0; i2 < tid; i2++) {
            float4 A = sbx[i2];
            float w = fminf(A.z, B.z) - fmaxf(A.x, B.x);
            float h = fminf(A.w, B.w) - fmaxf(A.y, B.y);
            float ovp = fmaxf(w, 0.f) * h;          // == ov when w,h > 0
            if (ovp > sar3[i2] + aj3) {             // rare candidate
                float ov = fmaxf(w, 0.f) * fmaxf(h, 0.f);
                float un = fmaxf(sar[i2] + sar[tid] - ov, 1e-6f);
                if (ov > 0.49999952f * un) {
                    if (ov > 0.50000048f * un ||
                        (double)ov > 0.5000000298023223876953125 * (double)un) {
                        viol = true; break;
                    }
                }
            }
        }
    }
    bool kp = (tid < TOPK) && !viol && (score > 0.05f);

    // ---- stable partition == sort by (masked desc, flat asc) ----
    bool isk = (tid < TOPK) && kp;
    bool isn = (tid < TOPK) && !kp;
    unsigned mK = __ballot_sync(0xffffffffu, isk);
    unsigned mN = __ballot_sync(0xffffffffu, isn);
    if (lane == 0) { s_wsum[wid] = __popc(mK); s_wsum2[wid] = __popc(mN); }
    __syncthreads();
    int cntK = 0, preK = 0, preN = 0;
#pragma unroll
    for (int w = 0; w < 8; w++) {
        cntK += s_wsum[w];
        if (w < wid) { preK += s_wsum[w]; preN += s_wsum2[w]; }
    }
    preK += __popc(mK & ((1u << lane) - 1u));
    preN += __popc(mN & ((1u << lane) - 1u));
    __syncthreads();                    // skey reads done; reuse as smk
    if (tid < TOPK) {
        float masked = kp ? score : -1.0f;
        int flat = c * TOPK + tid;
        ull key2 = ((ull)ford(masked) << 14) | (unsigned)(16383 - flat);
        int pos = kp ? preK : (cntK + preN);
        skey[pos] = key2;
    }
    __syncthreads();
    if (tid < MAXN)
        g_mkey[((size_t)b * NCLS + c) * MAXN + tid] = skey[tid];
}

// ============================================================================
// Kernel D: per-batch global top-100 over 80x100 keys (exact lax.top_k).
// ============================================================================
__global__ __launch_bounds__(1024) void merge_kernel(const float* __restrict__ f0,
                                                     const float* __restrict__ f1,
                                                     const float* __restrict__ f2,
                                                     const float* __restrict__ f3,
                                                     const float* __restrict__ f4,
                                                     float* __restrict__ out) {
    int b = blockIdx.x, tid = threadIdx.x;
    int lane = tid & 31, wid = tid >> 5;
    __shared__ int s_w3[32 * 3];
    __shared__ int s_tot[3];
    __shared__ int s_cnt;
    __shared__ ull skey[128];
    __shared__ int s_anchor[MAXN];

    const ull* mk = g_mkey + (size_t)b * NCLS * MAXN;
    ull w[8];
#pragma unroll
    for (int r = 0; r < 8; r++) {
        int i = r * 1024 + tid;
        w[r] = (i < NCLS * MAXN) ? mk[i] : 0ULL;
    }

    // 2-bit-per-round bit-search (keys unique -> terminates with count<=128)
    ull T = 0;
    int cur = 1 << 30;
    for (int bit = 45; bit >= 1; bit -= 2) {
        if (cur <= 128) break;
        ull cA = T | (1ULL << bit);
        ull cB = cA | (1ULL << (bit - 1));
        ull cC = T | (1ULL << (bit - 1));
        int nA = 0, nB = 0, nC = 0;
#pragma unroll
        for (int r = 0; r < 8; r++) {
            nA += (w[r] >= cA);
            nB += (w[r] >= cB);
            nC += (w[r] >= cC);
        }
        nA = (int)__reduce_add_sync(0xffffffffu, (unsigned)nA);
        nB = (int)__reduce_add_sync(0xffffffffu, (unsigned)nB);
        nC = (int)__reduce_add_sync(0xffffffffu, (unsigned)nC);
        if (lane == 0) {
            s_w3[wid * 3 + 0] = nA;
            s_w3[wid * 3 + 1] = nB;
            s_w3[wid * 3 + 2] = nC;
        }
        __syncthreads();
        if (wid < 3) {
            int x = s_w3[lane * 3 + wid];
#pragma unroll
            for (int off = 16; off; off >>= 1) x += __shfl_xor_sync(0xffffffffu, x, off);
            if (lane == 0) s_tot[wid] = x;
        }
        __syncthreads();
        int tA = s_tot[0], tB = s_tot[1], tC = s_tot[2];
        if (tA >= MAXN) {
            if (tB >= MAXN) { T = cB; cur = tB; }
            else            { T = cA; cur = tA; }
        } else {
            if (tC >= MAXN) { T = cC; cur = tC; }
        }
        __syncthreads();
    }

    if (tid == 0) s_cnt = 0;
    if (tid < 128) skey[tid] = ~0ULL;
    __syncthreads();
#pragma unroll
    for (int r = 0; r < 8; r++)
        if (w[r] >= T) { int p = atomicAdd(&s_cnt, 1); skey[p] = ~w[r]; }
    __syncthreads();

    for (int k2 = 2; k2 <= 128; k2 <<= 1)
        for (int j = k2 >> 1; j > 0; j >>= 1) {
            __syncthreads();
            if (tid < 128) {
                int ixj = tid ^ j;
                if (ixj > tid) {
                    ull A = skey[tid], B = skey[ixj];
                    bool up = ((tid & k2) == 0);
                    if ((A > B) == up) { skey[tid] = B; skey[ixj] = A; }
                }
            }
        }
    __syncthreads();

    if (tid < MAXN) {
        ull key = ~skey[tid];
        int flat = 16383 - (int)(key & 0x3FFFULL);
        int c = flat / TOPK, k = flat - c * TOPK;
        float val = iford((unsigned)(key >> 14));
        int anc = g_anms[((size_t)b * NCLS + c) * TOPK + k];
        float4 bx = *(const float4*)&g_bbox[((size_t)b * NANCH + anc) * 4];
        float* dr = out + ((size_t)b * MAXN + tid) * 5;
        dr[0] = bx.x; dr[1] = bx.y; dr[2] = bx.z; dr[3] = bx.w; dr[4] = val;
        out[(size_t)NB * MAXN * 5 + (size_t)b * MAXN + tid] = (float)c;
        s_anchor[tid] = anc;
    }
    __syncthreads();

    const float* cf[5] = { f0, f1, f2, f3, f4 };
    for (int idx = tid; idx < MAXN * NCOEF; idx += 1024) {
        int n = idx / NCOEF, j = idx - n * NCOEF;
        int anc = s_anchor[n];
        int lvl, S, sp, a;
        anch_decode(anc, lvl, S, sp, a);
        const float* cp = cf[lvl];
        g_csel[((size_t)b * MAXN + n) * NCOEF + j] =
            cp[((size_t)b * 96 + (size_t)(a * NCOEF + j)) * S + sp];
    }
}

// ============================================================================
// Kernel E: masks = sigmoid(proto @ csel^T). Occupancy-first redesign:
// 64 px/block, 2 px-pairs x 7 n per thread (acc = 28 regs), coeff smem
// un-duplicated (float), smem overlaid with store stage. 5 blocks/SM.
// ============================================================================
__global__ __launch_bounds__(256, 5) void mask_kernel(const float* __restrict__ proto,
                                                      float* __restrict__ out) {
    int b = blockIdx.y;
    int pix0 = blockIdx.x * 64;
    int tid = threadIdx.x;
    int pg = tid >> 4;       // 0..15 -> pairs pg, pg+16
    int ng = tid & 15;       // 0..15 -> n = ng*7 .. ng*7+6

    // smem overlay: [compute: scs(14848B) + sproto(8704B)] vs [stage: 25600B]
    __shared__ __align__(16) char smem_raw[25600];
    float* scs = (float*)smem_raw;                   // [112][33] floats
    ull*  sproto = (ull*)(smem_raw + 14848);         // [32][34] ull pairs
    float* stage = (float*)smem_raw;                 // 64*100 floats (epilogue)

    // ---- load coefficients (plain float, stride 33) ----
    for (int idx = tid; idx < 112 * 32; idx += 256) {
        int n = idx >> 5, k = idx & 31;
        float cv = (n < MAXN) ? g_csel[((size_t)b * MAXN + n) * NCOEF + k] : 0.f;
        scs[n * 33 + k] = cv;
    }
    // ---- load proto pairs (stride 34 ull) ----
    for (int idx = tid; idx < 64 * 8; idx += 256) {
        int px = idx >> 3, k4 = idx & 7;
        float4 pv = *(const float4*)(proto + ((size_t)b * 6400 + pix0 + px) * NCOEF + k4 * 4);
        float* dst = (float*)&sproto[(px >> 1) * 34 + k4 * 4];
        int h = px & 1;
        dst[0 + h] = pv.x; dst[2 + h] = pv.y; dst[4 + h] = pv.z; dst[6 + h] = pv.w;
    }
    __syncthreads();

    ull acc[2][7];
#pragma unroll
    for (int i = 0; i < 2; i++)
#pragma unroll
        for (int j = 0; j < 7; j++) acc[i][j] = 0ULL;

#pragma unroll 4
    for (int k = 0; k < NCOEF; k++) {
        ull pv0 = sproto[pg * 34 + k];
        ull pv1 = sproto[(pg + 16) * 34 + k];
#pragma unroll
        for (int j = 0; j < 7; j++) {
            float c = scs[(ng * 7 + j) * 33 + k];
            ull cv; asm("mov.b64 %0, {%1, %1};" : "=l"(cv) : "f"(c));
            fma2(acc[0][j], pv0, cv);
            fma2(acc[1][j], pv1, cv);
        }
    }
    __syncthreads();                     // compute smem dead; stage takes over

    // ---- single-phase epilogue: sigmoid + stage (all 256 threads) ----
#pragma unroll
    for (int i = 0; i < 2; i++) {
        int pl = (pg + 16 * i) * 2;      // local even pixel of this pair
#pragma unroll
        for (int j = 0; j < 7; j++) {
            int n = ng * 7 + j;
            if (n < MAXN) {
                float lo, hi;
                asm("mov.b64 {%0, %1}, %2;" : "=f"(lo), "=f"(hi) : "l"(acc[i][j]));
                stage[pl * 100 + n]       = __fdividef(1.0f, 1.0f + __expf(-lo));
                stage[(pl + 1) * 100 + n] = __fdividef(1.0f, 1.0f + __expf(-hi));
            }
        }
    }
    __syncthreads();

    size_t mbase = (size_t)NB * MAXN * 5 + (size_t)NB * MAXN;
    float4* o4 = (float4*)(out + mbase + ((size_t)b * 6400 + pix0) * MAXN);
    const float4* s4 = (const float4*)stage;
    for (int idx = tid; idx < 64 * MAXN / 4; idx += 256) o4[idx] = s4[idx];
}

// ============================================================================
extern "C" void kernel_launch(void* const* d_in, const int* in_sizes, int n_in,
                              void* d_out, int out_size) {
    const float* cls[5]; const float* box[5]; const float* cf[5];
    for (int i = 0; i < 5; i++) {
        cls[i] = (const float*)d_in[i];
        box[i] = (const float*)d_in[5 + i];
        cf[i]  = (const float*)d_in[10 + i];
    }
    const float* proto = (const float*)d_in[15];
    float* out = (float*)d_out;

    // host-side anchor bases (exact numpy float64 computation order)
    AB ab;
    const int BS[5] = {8, 16, 32, 64, 128};
    const double RT[3] = {0.5, 1.0, 2.0};
    for (int l = 0; l < 5; l++)
        for (int a = 0; a < 3; a++) {
            double hr = sqrt(RT[a]);
            double wr = 1.0 / hr;
            double ws = ((double)BS[l] * wr) * 3.0;
            double hs = ((double)BS[l] * hr) * 3.0;
            double cc = (double)BS[l] / 2.0;
            ab.v[l][a][0] = cc - 0.5 * ws;
            ab.v[l][a][1] = cc - 0.5 * hs;
            ab.v[l][a][2] = cc + 0.5 * ws;
            ab.v[l][a][3] = cc + 0.5 * hs;
        }

    dim3 gp(95, NB);       // 69 softmax blocks + 26 bbox blocks per batch
    pre_kernel<<<gp, 256>>>(cls[0], cls[1], cls[2], cls[3], cls[4],
                            box[0], box[1], box[2], box[3], box[4], ab);
    dim3 gn(NCLS, NB);
    nms_kernel<<<gn, 256>>>();
    merge_kernel<<<NB, 1024>>>(cf[0], cf[1], cf[2], cf[3], cf[4], out);
    dim3 gm(100, NB);
    mask_kernel<<<gm, 256>>>(proto, out);
}

// round 14
// speedup vs baseline: 1.0559x; 1.0427x over previous
#include <cuda_runtime.h>
#include <math.h>

#define NB 64
#define NANCH 6402
#define NANCHP 6416          // padded row (16B-aligned float4 rows); pad stays 0
#define NCLS 80
#define TOPK 200
#define MAXN 100
#define NCOEF 32

typedef unsigned long long ull;

// ---------------- scratch (__device__ globals: allocation-free rule) --------
__device__ __align__(16) float g_scoresT[(size_t)NB * NCLS * NANCHP]; // [b][c][anchP]
__device__ __align__(16) float g_bbox[(size_t)NB * NANCH * 4];        // decoded boxes
__device__ ull   g_mkey[(size_t)NB * NCLS * MAXN];   // per-class top-100 merge keys
__device__ int   g_anms[(size_t)NB * NCLS * TOPK];   // anchor id by rank k
__device__ __align__(16) float g_csel[(size_t)NB * MAXN * NCOEF];     // selected coeffs

struct AB { double v[5][3][4]; };   // host-computed anchor bases (numpy float64 path)

// order-preserving float<->uint (handles negatives for the -1.0 fillers)
__device__ __forceinline__ unsigned ford(float f) {
    unsigned u = __float_as_uint(f);
    return (u & 0x80000000u) ? ~u : (u | 0x80000000u);
}
__device__ __forceinline__ float iford(unsigned u) {
    return (u & 0x80000000u) ? __uint_as_float(u & 0x7FFFFFFFu) : __uint_as_float(~u);
}

__device__ __forceinline__ void fma2(ull& d, ull a, ull b) {
    asm("fma.rn.f32x2 %0, %1, %2, %0;" : "+l"(d) : "l"(a), "l"(b));
}

__device__ __forceinline__ void anch_decode(int anc, int& lvl, int& S, int& sp, int& a) {
    if (anc < 4800)      { lvl = 0; S = 1600; anc -= 0; }
    else if (anc < 6000) { lvl = 1; S = 400;  anc -= 4800; }
    else if (anc < 6300) { lvl = 2; S = 100;  anc -= 6000; }
    else if (anc < 6375) { lvl = 3; S = 25;   anc -= 6300; }
    else                 { lvl = 4; S = 9;    anc -= 6375; }
    sp = anc / 3;
    a  = anc - sp * 3;
}

// block-wide exclusive-scan of x; returns this thread's exclusive offset,
// sets total. Uses wsum[NW]; 2 internal barriers.
template <int NW>
__device__ __forceinline__ int block_scan(int x, int lane, int wid,
                                          volatile int* wsum, int& total) {
    int inc = x;
#pragma unroll
    for (int off = 1; off < 32; off <<= 1) {
        int y = __shfl_up_sync(0xffffffffu, inc, off);
        if (lane >= off) inc += y;
    }
    if (lane == 31) wsum[wid] = inc;
    __syncthreads();
    int woff = 0, tot = 0;
#pragma unroll
    for (int w = 0; w < NW; w++) { int s = wsum[w]; if (w < wid) woff += s; tot += s; }
    total = tot;
    __syncthreads();
    return woff + (inc - x);
}

// ============================================================================
// Kernel A: fused all-level softmax -> g_scoresT (dedicated 96-thread blocks).
// ============================================================================
__global__ __launch_bounds__(96) void softmax_kernel(const float* __restrict__ c0,
                                                     const float* __restrict__ c1,
                                                     const float* __restrict__ c2,
                                                     const float* __restrict__ c3,
                                                     const float* __restrict__ c4) {
    int bx = blockIdx.x;
    const float* cls; int S, aoff, x0;
    if (bx < 50)      { cls = c0; S = 1600; aoff = 0;    x0 = bx; }
    else if (bx < 63) { cls = c1; S = 400;  aoff = 4800; x0 = bx - 50; }
    else if (bx < 67) { cls = c2; S = 100;  aoff = 6000; x0 = bx - 63; }
    else if (bx < 68) { cls = c3; S = 25;   aoff = 6300; x0 = 0; }
    else              { cls = c4; S = 9;    aoff = 6375; x0 = 0; }

    int b = blockIdx.y;
    int lane = threadIdx.x & 31;
    int a = threadIdx.x >> 5;
    int sp = x0 * 32 + lane;
    __shared__ float sbuf[NCLS * 96];

    if (sp < S) {
        const float* base = cls + ((size_t)b * 243 + (size_t)a * 81) * S + sp;
        float v[81];
#pragma unroll
        for (int c = 0; c < 81; c++) v[c] = base[(size_t)c * S];
        float m = v[0];
#pragma unroll
        for (int c = 1; c < 81; c++) m = fmaxf(m, v[c]);
        float s = 0.f;
#pragma unroll
        for (int c = 0; c < 81; c++) { v[c] = expf(v[c] - m); s += v[c]; }
        float inv = 1.0f / s;
#pragma unroll
        for (int c = 0; c < 80; c++) sbuf[c * 96 + lane * 3 + a] = v[c] * inv;
    } else {
#pragma unroll
        for (int c = 0; c < 80; c++) sbuf[c * 96 + lane * 3 + a] = 0.f;
    }
    __syncthreads();

    int remain = (S - x0 * 32) * 3;
    int cnt = remain < 96 ? remain : 96;
    size_t obase = (size_t)b * NCLS * NANCHP + aoff + (size_t)x0 * 96;
    int t = threadIdx.x;
    if (t < cnt) {
        for (int c = 0; c < NCLS; c++)
            g_scoresT[obase + (size_t)c * NANCHP + t] = sbuf[c * 96 + t];
    }
}

// ============================================================================
// Kernel B: delta2bbox using host-precomputed double anchor bases.
// ============================================================================
__global__ __launch_bounds__(256) void bbox_kernel(const float* __restrict__ b0,
                                                   const float* __restrict__ b1,
                                                   const float* __restrict__ b2,
                                                   const float* __restrict__ b3,
                                                   const float* __restrict__ b4,
                                                   AB ab) {
    int gid = blockIdx.x * blockDim.x + threadIdx.x;
    if (gid >= NB * NANCH) return;
    int b = gid / NANCH, anc = gid - b * NANCH;

    int lvl, S, sp, a;
    anch_decode(anc, lvl, S, sp, a);
    int f, bs;
    const float* bp;
    switch (lvl) {
        case 0: f = 40; bs = 8;   bp = b0; break;
        case 1: f = 20; bs = 16;  bp = b1; break;
        case 2: f = 10; bs = 32;  bp = b2; break;
        case 3: f = 5;  bs = 64;  bp = b3; break;
        default: f = 3; bs = 128; bp = b4; break;
    }
    int x = sp % f, y = sp / f;
    double shx = (double)(x * bs), shy = (double)(y * bs);
    float ax1 = (float)(ab.v[lvl][a][0] + shx);
    float ay1 = (float)(ab.v[lvl][a][1] + shy);
    float ax2 = (float)(ab.v[lvl][a][2] + shx);
    float ay2 = (float)(ab.v[lvl][a][3] + shy);

    size_t di = ((size_t)b * 12 + (size_t)a * 4) * S + sp;
    float dx = bp[di] * 0.1f;
    float dy = bp[di + (size_t)S] * 0.1f;
    float dw = bp[di + 2 * (size_t)S] * 0.2f;
    float dh = bp[di + 3 * (size_t)S] * 0.2f;
    const float R = 4.135166556742356f;
    dw = fminf(fmaxf(dw, -R), R);
    dh = fminf(fmaxf(dh, -R), R);

    float px = (ax1 + ax2) * 0.5f, py = (ay1 + ay2) * 0.5f;
    float pw = ax2 - ax1, ph = ay2 - ay1;
    float gx = px + pw * dx, gy = py + ph * dy;
    float gw = pw * expf(dw), gh = ph * expf(dh);
    float4 o;
    o.x = fminf(fmaxf(gx - 0.5f * gw, 0.f), 320.f);
    o.y = fminf(fmaxf(gy - 0.5f * gh, 0.f), 320.f);
    o.z = fminf(fmaxf(gx + 0.5f * gw, 0.f), 320.f);
    o.w = fminf(fmaxf(gy + 0.5f * gh, 0.f), 320.f);
    *(float4*)&g_bbox[(size_t)gid * 4] = o;
}

// ============================================================================
// Kernel C (fused): per-(batch,class): exact stable top-200 (early-exit
// bit-search + scan-compaction), bitonic sort, fast-NMS (score-gated,
// single-predicate hot path, exact rare path), stable partition.
// ============================================================================
__global__ __launch_bounds__(256, 6) void nms_kernel() {
    int c = blockIdx.x, b = blockIdx.y;
    int tid = threadIdx.x;
    int lane = tid & 31, wid = tid >> 5;
    __shared__ int s_hist[2][8];
    __shared__ int s_wsum[8];
    __shared__ int s_wsum2[8];
    __shared__ int s_taken;
    __shared__ ull skey[256];
    __shared__ float4 sbx[TOPK];
    __shared__ float sar[TOPK];      // raw areas (exact path)
    __shared__ float sar3[TOPK];     // C3-prescaled areas (hot path)

    const float* srow = g_scoresT + ((size_t)b * NCLS + c) * NANCHP;
    unsigned v[28];
#pragma unroll
    for (int r = 0; r < 7; r++) {
        int f4 = r * 256 + tid;
        if (f4 < NANCHP / 4) {
            float4 t = *(const float4*)(srow + f4 * 4);
            v[r * 4 + 0] = __float_as_uint(t.x);
            v[r * 4 + 1] = __float_as_uint(t.y);
            v[r * 4 + 2] = __float_as_uint(t.z);
            v[r * 4 + 3] = __float_as_uint(t.w);
        } else {
            v[r * 4 + 0] = v[r * 4 + 1] = v[r * 4 + 2] = v[r * 4 + 3] = 0u;
        }
    }

    // ---- early-exit bit-search: 200 <= count(v >= T) <= 256, 1 barrier/round --
    unsigned T = 0;
    int cur = 1 << 30, pp = 0;
    for (int bit = 29; bit >= 0; bit--) {
        if (cur <= 256) break;
        unsigned cand = T | (1u << bit);
        int cnt = 0;
#pragma unroll
        for (int e = 0; e < 28; e++) cnt += (v[e] >= cand);
        cnt = (int)__reduce_add_sync(0xffffffffu, (unsigned)cnt);
        if (lane == 0) s_hist[pp][wid] = cnt;
        __syncthreads();
        int tot = 0;
#pragma unroll
        for (int w = 0; w < 8; w++) tot += s_hist[pp][w];
        if (tot >= TOPK) { T = cand; cur = tot; }
        pp ^= 1;
    }

    skey[tid] = ~0ULL;
    __syncthreads();

    if (cur <= 256) {
        // collect all v >= T via scan (no atomics); sort restores exact order
        int ct = 0;
#pragma unroll
        for (int e = 0; e < 28; e++) ct += (v[e] >= T);
        int tot;
        int pos = block_scan<8>(ct, lane, wid, s_wsum, tot);
#pragma unroll
        for (int r = 0; r < 7; r++)
#pragma unroll
            for (int q = 0; q < 4; q++) {
                int e = r * 4 + q;
                if (v[e] >= T) {
                    int i = (r * 256 + tid) * 4 + q;
                    ull key = ((ull)v[e] << 32) | (unsigned)(~(unsigned)i);
                    skey[pos++] = ~key;
                }
            }
        __syncthreads();
    } else {
        // pathological mass-tie fallback: v > T, then equal-T smallest indices
        int cg = 0;
#pragma unroll
        for (int e = 0; e < 28; e++) cg += (v[e] > T);
        int cnt_gt;
        int pos = block_scan<8>(cg, lane, wid, s_wsum, cnt_gt);
        int need_eq = TOPK - cnt_gt;
#pragma unroll
        for (int r = 0; r < 7; r++)
#pragma unroll
            for (int q = 0; q < 4; q++) {
                int e = r * 4 + q;
                if (v[e] > T) {
                    int i = (r * 256 + tid) * 4 + q;
                    ull key = ((ull)v[e] << 32) | (unsigned)(~(unsigned)i);
                    skey[pos++] = ~key;
                }
            }
        if (tid == 0) s_taken = 0;
        __syncthreads();
        // i-order = (r, tid, q) lexicographic == ascending anchor index
        for (int r = 0; r < 7; r++) {
            __syncthreads();
            int taken = s_taken;
            if (taken >= need_eq) continue;
            int ec = 0;
            bool mq[4];
#pragma unroll
            for (int q = 0; q < 4; q++) {
                mq[q] = (v[r * 4 + q] == T);
                ec += mq[q];
            }
            int tot2;
            int base = block_scan<8>(ec, lane, wid, s_wsum, tot2);
            int o = taken + base;
#pragma unroll
            for (int q = 0; q < 4; q++)
                if (mq[q]) {
                    if (o < need_eq) {
                        int i = (r * 256 + tid) * 4 + q;
                        ull key = ((ull)T << 32) | (unsigned)(~(unsigned)i);
                        skey[cnt_gt + o] = ~key;
                    }
                    o++;
                }
            if (tid == 0) s_taken = taken + tot2;
        }
        __syncthreads();
    }

    // ---- bitonic sort 256 (ascending ~key == desc score, asc anchor) ----
    for (int k2 = 2; k2 <= 256; k2 <<= 1)
        for (int j = k2 >> 1; j > 0; j >>= 1) {
            __syncthreads();
            int ixj = tid ^ j;
            if (ixj > tid) {
                ull A = skey[tid], B = skey[ixj];
                bool up = ((tid & k2) == 0);
                if ((A > B) == up) { skey[tid] = B; skey[ixj] = A; }
            }
        }
    __syncthreads();

    // ---- gather boxes for fast-NMS ----
    const float C3 = 0.3333290f;
    float score = -2.f;
    if (tid < TOPK) {
        ull key = ~skey[tid];
        int anc = (int)(~(unsigned)(key & 0xFFFFFFFFu));
        score = __uint_as_float((unsigned)(key >> 32));
        float4 bx = *(const float4*)&g_bbox[((size_t)b * NANCH + anc) * 4];
        sbx[tid] = bx;
        float ar = (bx.z - bx.x) * (bx.w - bx.y);
        sar[tid] = ar;
        sar3[tid] = C3 * ar;
        g_anms[((size_t)b * NCLS + c) * TOPK + tid] = anc;
    }
    __syncthreads();

    // ---- fast-NMS (score-gated; exact) ----
    bool viol = false;
    if (tid > 0 && tid < TOPK && score > 0.05f) {
        float4 B = sbx[tid];
        float aj3 = sar3[tid];
#pragma unroll 4
        for (int i2 = 0; i2 < tid; i2++) {
            float4 A = sbx[i2];
            float w = fminf(A.z, B.z) - fmaxf(A.x, B.x);
            float h = fminf(A.w, B.w) - fmaxf(A.y, B.y);
            float ovp = fmaxf(w, 0.f) * h;          // == ov when w,h > 0
            if (ovp > sar3[i2] + aj3) {             // rare candidate
                float ov = fmaxf(w, 0.f) * fmaxf(h, 0.f);
                float un = fmaxf(sar[i2] + sar[tid] - ov, 1e-6f);
                if (ov > 0.49999952f * un) {
                    if (ov > 0.50000048f * un ||
                        (double)ov > 0.5000000298023223876953125 * (double)un) {
                        viol = true; break;
                    }
                }
            }
        }
    }
    bool kp = (tid < TOPK) && !viol && (score > 0.05f);

    // ---- stable partition == sort by (masked desc, flat asc) ----
    bool isk = (tid < TOPK) && kp;
    bool isn = (tid < TOPK) && !kp;
    unsigned mK = __ballot_sync(0xffffffffu, isk);
    unsigned mN = __ballot_sync(0xffffffffu, isn);
    if (lane == 0) { s_wsum[wid] = __popc(mK); s_wsum2[wid] = __popc(mN); }
    __syncthreads();
    int cntK = 0, preK = 0, preN = 0;
#pragma unroll
    for (int w = 0; w < 8; w++) {
        cntK += s_wsum[w];
        if (w < wid) { preK += s_wsum[w]; preN += s_wsum2[w]; }
    }
    preK += __popc(mK & ((1u << lane) - 1u));
    preN += __popc(mN & ((1u << lane) - 1u));
    __syncthreads();                    // skey reads done; reuse as smk
    if (tid < TOPK) {
        float masked = kp ? score : -1.0f;
        int flat = c * TOPK + tid;
        ull key2 = ((ull)ford(masked) << 14) | (unsigned)(16383 - flat);
        int pos = kp ? preK : (cntK + preN);
        skey[pos] = key2;
    }
    __syncthreads();
    if (tid < MAXN)
        g_mkey[((size_t)b * NCLS + c) * MAXN + tid] = skey[tid];
}

// ============================================================================
// Kernel D: per-batch global top-100 over 80x100 keys (exact lax.top_k).
// ============================================================================
__global__ __launch_bounds__(1024) void merge_kernel(const float* __restrict__ f0,
                                                     const float* __restrict__ f1,
                                                     const float* __restrict__ f2,
                                                     const float* __restrict__ f3,
                                                     const float* __restrict__ f4,
                                                     float* __restrict__ out) {
    int b = blockIdx.x, tid = threadIdx.x;
    int lane = tid & 31, wid = tid >> 5;
    __shared__ int s_w3[32 * 3];
    __shared__ int s_tot[3];
    __shared__ int s_cnt;
    __shared__ ull skey[128];
    __shared__ int s_anchor[MAXN];

    const ull* mk = g_mkey + (size_t)b * NCLS * MAXN;
    ull w[8];
#pragma unroll
    for (int r = 0; r < 8; r++) {
        int i = r * 1024 + tid;
        w[r] = (i < NCLS * MAXN) ? mk[i] : 0ULL;
    }

    // 2-bit-per-round bit-search (keys unique -> terminates with count<=128)
    ull T = 0;
    int cur = 1 << 30;
    for (int bit = 45; bit >= 1; bit -= 2) {
        if (cur <= 128) break;
        ull cA = T | (1ULL << bit);
        ull cB = cA | (1ULL << (bit - 1));
        ull cC = T | (1ULL << (bit - 1));
        int nA = 0, nB = 0, nC = 0;
#pragma unroll
        for (int r = 0; r < 8; r++) {
            nA += (w[r] >= cA);
            nB += (w[r] >= cB);
            nC += (w[r] >= cC);
        }
        nA = (int)__reduce_add_sync(0xffffffffu, (unsigned)nA);
        nB = (int)__reduce_add_sync(0xffffffffu, (unsigned)nB);
        nC = (int)__reduce_add_sync(0xffffffffu, (unsigned)nC);
        if (lane == 0) {
            s_w3[wid * 3 + 0] = nA;
            s_w3[wid * 3 + 1] = nB;
            s_w3[wid * 3 + 2] = nC;
        }
        __syncthreads();
        if (wid < 3) {
            int x = s_w3[lane * 3 + wid];
#pragma unroll
            for (int off = 16; off; off >>= 1) x += __shfl_xor_sync(0xffffffffu, x, off);
            if (lane == 0) s_tot[wid] = x;
        }
        __syncthreads();
        int tA = s_tot[0], tB = s_tot[1], tC = s_tot[2];
        if (tA >= MAXN) {
            if (tB >= MAXN) { T = cB; cur = tB; }
            else            { T = cA; cur = tA; }
        } else {
            if (tC >= MAXN) { T = cC; cur = tC; }
        }
        __syncthreads();
    }

    if (tid == 0) s_cnt = 0;
    if (tid < 128) skey[tid] = ~0ULL;
    __syncthreads();
#pragma unroll
    for (int r = 0; r < 8; r++)
        if (w[r] >= T) { int p = atomicAdd(&s_cnt, 1); skey[p] = ~w[r]; }
    __syncthreads();

    for (int k2 = 2; k2 <= 128; k2 <<= 1)
        for (int j = k2 >> 1; j > 0; j >>= 1) {
            __syncthreads();
            if (tid < 128) {
                int ixj = tid ^ j;
                if (ixj > tid) {
                    ull A = skey[tid], B = skey[ixj];
                    bool up = ((tid & k2) == 0);
                    if ((A > B) == up) { skey[tid] = B; skey[ixj] = A; }
                }
            }
        }
    __syncthreads();

    if (tid < MAXN) {
        ull key = ~skey[tid];
        int flat = 16383 - (int)(key & 0x3FFFULL);
        int c = flat / TOPK, k = flat - c * TOPK;
        float val = iford((unsigned)(key >> 14));
        int anc = g_anms[((size_t)b * NCLS + c) * TOPK + k];
        float4 bx = *(const float4*)&g_bbox[((size_t)b * NANCH + anc) * 4];
        float* dr = out + ((size_t)b * MAXN + tid) * 5;
        dr[0] = bx.x; dr[1] = bx.y; dr[2] = bx.z; dr[3] = bx.w; dr[4] = val;
        out[(size_t)NB * MAXN * 5 + (size_t)b * MAXN + tid] = (float)c;
        s_anchor[tid] = anc;
    }
    __syncthreads();

    const float* cf[5] = { f0, f1, f2, f3, f4 };
    for (int idx = tid; idx < MAXN * NCOEF; idx += 1024) {
        int n = idx / NCOEF, j = idx - n * NCOEF;
        int anc = s_anchor[n];
        int lvl, S, sp, a;
        anch_decode(anc, lvl, S, sp, a);
        const float* cp = cf[lvl];
        g_csel[((size_t)b * MAXN + n) * NCOEF + j] =
            cp[((size_t)b * 96 + (size_t)(a * NCOEF + j)) * S + sp];
    }
}

// ============================================================================
// Kernel E: masks = sigmoid(proto @ csel^T). k-vectorized: per 2 k-steps one
// LDS.128 per proto pair and one LDS.64 per coeff (halves LDS instruction
// count). 64 px/block, 2 px-pairs x 7 n per thread, smem overlaid with stage.
// ============================================================================
__global__ __launch_bounds__(256, 4) void mask_kernel(const float* __restrict__ proto,
                                                      float* __restrict__ out) {
    int b = blockIdx.y;
    int pix0 = blockIdx.x * 64;
    int tid = threadIdx.x;
    int pg = tid >> 4;       // 0..15 -> pairs pg, pg+16
    int ng = tid & 15;       // 0..15 -> n = ng*7 .. ng*7+6

    // smem overlay: [compute: scs(15232B) + sproto(8704B)=23936B] vs [stage 25600B]
    __shared__ __align__(16) char smem_raw[25600];
    float* scs = (float*)smem_raw;                   // [112][34] floats (8B-aligned rows)
    ull*  sproto = (ull*)(smem_raw + 15232);         // [32][34] ull pairs (16B-aligned rows)
    float* stage = (float*)smem_raw;                 // 64*100 floats (epilogue)

    // ---- load coefficients (plain float, stride 34 -> float2-aligned) ----
    for (int idx = tid; idx < 112 * 32; idx += 256) {
        int n = idx >> 5, k = idx & 31;
        float cv = (n < MAXN) ? g_csel[((size_t)b * MAXN + n) * NCOEF + k] : 0.f;
        scs[n * 34 + k] = cv;
    }
    // ---- load proto pairs (stride 34 ull; row start 16B-aligned) ----
    for (int idx = tid; idx < 64 * 8; idx += 256) {
        int px = idx >> 3, k4 = idx & 7;
        float4 pv = *(const float4*)(proto + ((size_t)b * 6400 + pix0 + px) * NCOEF + k4 * 4);
        float* dst = (float*)&sproto[(px >> 1) * 34 + k4 * 4];
        int h = px & 1;
        dst[0 + h] = pv.x; dst[2 + h] = pv.y; dst[4 + h] = pv.z; dst[6 + h] = pv.w;
    }
    __syncthreads();

    ull acc[2][7];
#pragma unroll
    for (int i = 0; i < 2; i++)
#pragma unroll
        for (int j = 0; j < 7; j++) acc[i][j] = 0ULL;

#pragma unroll 4
    for (int kk = 0; kk < NCOEF / 2; kk++) {        // k = 2*kk, 2*kk+1
        ulonglong2 p0 = *(const ulonglong2*)&sproto[pg * 34 + 2 * kk];
        ulonglong2 p1 = *(const ulonglong2*)&sproto[(pg + 16) * 34 + 2 * kk];
#pragma unroll
        for (int j = 0; j < 7; j++) {
            float2 cc = *(const float2*)&scs[(ng * 7 + j) * 34 + 2 * kk];
            ull cva, cvb;
            asm("mov.b64 %0, {%1, %1};" : "=l"(cva) : "f"(cc.x));
            asm("mov.b64 %0, {%1, %1};" : "=l"(cvb) : "f"(cc.y));
            fma2(acc[0][j], p0.x, cva);
            fma2(acc[0][j], p0.y, cvb);
            fma2(acc[1][j], p1.x, cva);
            fma2(acc[1][j], p1.y, cvb);
        }
    }
    __syncthreads();                     // compute smem dead; stage takes over

    // ---- single-phase epilogue: sigmoid + stage (all 256 threads) ----
#pragma unroll
    for (int i = 0; i < 2; i++) {
        int pl = (pg + 16 * i) * 2;      // local even pixel of this pair
#pragma unroll
        for (int j = 0; j < 7; j++) {
            int n = ng * 7 + j;
            if (n < MAXN) {
                float lo, hi;
                asm("mov.b64 {%0, %1}, %2;" : "=f"(lo), "=f"(hi) : "l"(acc[i][j]));
                stage[pl * 100 + n]       = __fdividef(1.0f, 1.0f + __expf(-lo));
                stage[(pl + 1) * 100 + n] = __fdividef(1.0f, 1.0f + __expf(-hi));
            }
        }
    }
    __syncthreads();

    size_t mbase = (size_t)NB * MAXN * 5 + (size_t)NB * MAXN;
    float4* o4 = (float4*)(out + mbase + ((size_t)b * 6400 + pix0) * MAXN);
    const float4* s4 = (const float4*)stage;
    for (int idx = tid; idx < 64 * MAXN / 4; idx += 256) o4[idx] = s4[idx];
}

// ============================================================================
extern "C" void kernel_launch(void* const* d_in, const int* in_sizes, int n_in,
                              void* d_out, int out_size) {
    const float* cls[5]; const float* box[5]; const float* cf[5];
    for (int i = 0; i < 5; i++) {
        cls[i] = (const float*)d_in[i];
        box[i] = (const float*)d_in[5 + i];
        cf[i]  = (const float*)d_in[10 + i];
    }
    const float* proto = (const float*)d_in[15];
    float* out = (float*)d_out;

    // host-side anchor bases (exact numpy float64 computation order)
    AB ab;
    const int BS[5] = {8, 16, 32, 64, 128};
    const double RT[3] = {0.5, 1.0, 2.0};
    for (int l = 0; l < 5; l++)
        for (int a = 0; a < 3; a++) {
            double hr = sqrt(RT[a]);
            double wr = 1.0 / hr;
            double ws = ((double)BS[l] * wr) * 3.0;
            double hs = ((double)BS[l] * hr) * 3.0;
            double cc = (double)BS[l] / 2.0;
            ab.v[l][a][0] = cc - 0.5 * ws;
            ab.v[l][a][1] = cc - 0.5 * hs;
            ab.v[l][a][2] = cc + 0.5 * ws;
            ab.v[l][a][3] = cc + 0.5 * hs;
        }

    dim3 gs(69, NB);
    softmax_kernel<<<gs, 96>>>(cls[0], cls[1], cls[2], cls[3], cls[4]);
    bbox_kernel<<<(NB * NANCH + 255) / 256, 256>>>(box[0], box[1], box[2], box[3], box[4], ab);
    dim3 gn(NCLS, NB);
    nms_kernel<<<gn, 256>>>();
    merge_kernel<<<NB, 1024>>>(cf[0], cf[1], cf[2], cf[3], cf[4], out);
    dim3 gm(100, NB);
    mask_kernel<<<gm, 256>>>(proto, out);
}